// round 6
// baseline (speedup 1.0000x reference)
#include <cuda_runtime.h>
#include <cuda_fp16.h>
#include <cstdint>

#define N_NODES 100000
#define N_EDGES 3200000
#define D_IN    256
#define D_HID   256
#define D_OUT   128

// ---------------- scratch (static device globals; no allocation) ----------------
__device__ __half g_h1  [(size_t)N_NODES * D_HID];   // X @ W1            (half)
__device__ __half g_agg1[(size_t)N_NODES * D_HID];   // relu(agg + b1)    (half)
__device__ __half g_h2  [(size_t)N_NODES * D_OUT];   // agg1 @ W2         (half)
__device__ int    g_csrc [N_EDGES];                  // CSR: src node per edge (dst-sorted)
__device__ float  g_cnorm[N_EDGES];                  // CSR: edge norm
__device__ int    g_rowptr[N_NODES + 1];
__device__ int    g_cursor[N_NODES];
__device__ int    g_cnt   [N_NODES];                 // incoming-edge count (no self loop)
__device__ float  g_dinv  [N_NODES];
__device__ float  g_dinv2 [N_NODES];

// ---------------- prep ----------------
__global__ void k_zero_cnt(int n) {
    int i = blockIdx.x * blockDim.x + threadIdx.x;
    if (i < n) g_cnt[i] = 0;
}

// edge_index is int32 (JAX x64 disabled)
__global__ void k_count(const int* __restrict__ ei, int nE) {
    int e = blockIdx.x * blockDim.x + threadIdx.x;
    if (e >= nE) return;
    atomicAdd(&g_cnt[ei[nE + e]], 1);
}

// single-block exclusive scan over g_cnt -> g_rowptr, init g_cursor, compute dinv
__global__ void k_scan(int n) {
    const int T = 1024;
    __shared__ int s[T];
    int t = threadIdx.x;
    int items = (n + T - 1) / T;
    int base = t * items;

    int sum = 0;
    for (int j = 0; j < items; j++) {
        int idx = base + j;
        if (idx < n) sum += g_cnt[idx];
    }
    s[t] = sum;
    __syncthreads();
    for (int off = 1; off < T; off <<= 1) {
        int v = (t >= off) ? s[t - off] : 0;
        __syncthreads();
        s[t] += v;
        __syncthreads();
    }
    int run = s[t] - sum;   // exclusive prefix
    for (int j = 0; j < items; j++) {
        int idx = base + j;
        if (idx < n) {
            int c = g_cnt[idx];
            g_rowptr[idx] = run;
            g_cursor[idx] = run;
            run += c;
            float r = rsqrtf((float)(c + 1));   // +1 self loop
            g_dinv[idx]  = r;
            g_dinv2[idx] = r * r;
        }
    }
    if (t == T - 1) g_rowptr[n] = s[T - 1];
}

__global__ void k_fill(const int* __restrict__ ei, int nE) {
    int e = blockIdx.x * blockDim.x + threadIdx.x;
    if (e >= nE) return;
    int s = ei[e];
    int d = ei[nE + e];
    int pos = atomicAdd(&g_cursor[d], 1);
    g_csrc[pos]  = s;
    g_cnorm[pos] = g_dinv[s] * g_dinv[d];
}

// ---------------- TF32 tensor-core GEMM: H(half) = A[M,256] @ W[256,N] --------
// Block tile 128x128, BK=16, 8 warps (2Mx4N), warp tile 64x32 (4x4 m16n8k8 atoms).
// A_HALF selects half-precision A (agg1). Output stored as half2.
__device__ __forceinline__ uint32_t f2tf32(float f) {
    uint32_t r;
    asm("cvt.rna.tf32.f32 %0, %1;" : "=r"(r) : "f"(f));
    return r;
}

template<int N, bool A_HALF>
__global__ __launch_bounds__(256, 2)
void gemm_tf32(const void* __restrict__ Av, const float* __restrict__ W,
               __half* __restrict__ H, int M)
{
    constexpr int K  = 256;
    constexpr int BK = 16;
    constexpr int ST = 136;                 // smem row stride (floats)
    __shared__ float As[BK * ST];           // [k][m] transposed
    __shared__ float Bs[BK * ST];           // [k][n]

    const int tid   = threadIdx.x;
    const int lane  = tid & 31;
    const int wid   = tid >> 5;
    const int warpM = wid & 1;
    const int warpN = wid >> 1;
    const int g     = lane >> 2;            // groupID 0..7
    const int tig   = lane & 3;             // thread-in-group 0..3

    const int bm = blockIdx.y * 128;
    const int bn = blockIdx.x * 128;

    float c[4][4][4];
    #pragma unroll
    for (int am = 0; am < 4; am++)
        #pragma unroll
        for (int an = 0; an < 4; an++)
            #pragma unroll
            for (int r = 0; r < 4; r++) c[am][an][r] = 0.f;

    for (int k0 = 0; k0 < K; k0 += BK) {
        // ---- load A tile (128 m x 16 k) -> As[k][m] (tf32-rounded) ----
        if (A_HALF) {
            const __half* A = (const __half*)Av;
            int row = tid & 127;            // 0..127
            int hs  = tid >> 7;             // 0..1 (k-half, 8 halves each)
            int gm  = bm + row;
            uint4 raw = make_uint4(0, 0, 0, 0);
            if (gm < M)
                raw = *(const uint4*)(A + (size_t)gm * K + k0 + hs * 8);
            const __half2* hp = (const __half2*)&raw;
            #pragma unroll
            for (int j = 0; j < 4; j++) {
                float2 f = __half22float2(hp[j]);
                As[(hs * 8 + j * 2 + 0) * ST + row] = __uint_as_float(f2tf32(f.x));
                As[(hs * 8 + j * 2 + 1) * ST + row] = __uint_as_float(f2tf32(f.y));
            }
        } else {
            const float* A = (const float*)Av;
            #pragma unroll
            for (int it = 0; it < 2; it++) {
                int idx = tid + it * 256;
                int row = idx >> 2;
                int kq  = (idx & 3) * 4;
                float4 av = make_float4(0.f, 0.f, 0.f, 0.f);
                int gm = bm + row;
                if (gm < M)
                    av = *(const float4*)(A + (size_t)gm * K + k0 + kq);
                As[(kq + 0) * ST + row] = __uint_as_float(f2tf32(av.x));
                As[(kq + 1) * ST + row] = __uint_as_float(f2tf32(av.y));
                As[(kq + 2) * ST + row] = __uint_as_float(f2tf32(av.z));
                As[(kq + 3) * ST + row] = __uint_as_float(f2tf32(av.w));
            }
        }
        // ---- load B tile (16 k x 128 n) ----
        #pragma unroll
        for (int it = 0; it < 2; it++) {
            int idx  = tid + it * 256;
            int krow = idx >> 5;
            int nq   = (idx & 31) * 4;
            float4 bv = *(const float4*)(W + (size_t)(k0 + krow) * N + bn + nq);
            float4 bt;
            bt.x = __uint_as_float(f2tf32(bv.x));
            bt.y = __uint_as_float(f2tf32(bv.y));
            bt.z = __uint_as_float(f2tf32(bv.z));
            bt.w = __uint_as_float(f2tf32(bv.w));
            *(float4*)&Bs[krow * ST + nq] = bt;
        }
        __syncthreads();

        #pragma unroll
        for (int kk = 0; kk < BK; kk += 8) {
            uint32_t af[4][4];
            #pragma unroll
            for (int am = 0; am < 4; am++) {
                int m0 = warpM * 64 + am * 16 + g;
                af[am][0] = __float_as_uint(As[(kk + tig)     * ST + m0]);
                af[am][1] = __float_as_uint(As[(kk + tig)     * ST + m0 + 8]);
                af[am][2] = __float_as_uint(As[(kk + tig + 4) * ST + m0]);
                af[am][3] = __float_as_uint(As[(kk + tig + 4) * ST + m0 + 8]);
            }
            uint32_t bf[4][2];
            #pragma unroll
            for (int an = 0; an < 4; an++) {
                int n0 = warpN * 32 + an * 8 + g;
                bf[an][0] = __float_as_uint(Bs[(kk + tig)     * ST + n0]);
                bf[an][1] = __float_as_uint(Bs[(kk + tig + 4) * ST + n0]);
            }
            #pragma unroll
            for (int am = 0; am < 4; am++)
                #pragma unroll
                for (int an = 0; an < 4; an++) {
                    asm volatile(
                        "mma.sync.aligned.m16n8k8.row.col.f32.tf32.tf32.f32 "
                        "{%0,%1,%2,%3}, {%4,%5,%6,%7}, {%8,%9}, {%0,%1,%2,%3};"
                        : "+f"(c[am][an][0]), "+f"(c[am][an][1]),
                          "+f"(c[am][an][2]), "+f"(c[am][an][3])
                        : "r"(af[am][0]), "r"(af[am][1]), "r"(af[am][2]), "r"(af[am][3]),
                          "r"(bf[an][0]), "r"(bf[an][1]));
                }
        }
        __syncthreads();
    }

    // ---- epilogue: store half2 pairs ----
    #pragma unroll
    for (int am = 0; am < 4; am++) {
        int row = bm + warpM * 64 + am * 16 + g;
        #pragma unroll
        for (int an = 0; an < 4; an++) {
            int col = bn + warpN * 32 + an * 8 + tig * 2;
            if (row < M)
                *(__half2*)(H + (size_t)row * N + col) =
                    __floats2half2_rn(c[am][an][0], c[am][an][1]);
            if (row + 8 < M)
                *(__half2*)(H + (size_t)(row + 8) * N + col) =
                    __floats2half2_rn(c[am][an][2], c[am][an][3]);
        }
    }
}

// ---------------- CSR aggregation over half rows, fp32 accumulate -------------
// Lane = 8 halves (16B). L = D/8 lanes/node, NPB = 256/L nodes per block.
// ACT 0: relu -> half output. ACT 1: sigmoid -> fp32 output.
__device__ __forceinline__ void unpack8(uint4 r, float* f) {
    const __half2* hp = (const __half2*)&r;
    #pragma unroll
    for (int j = 0; j < 4; j++) {
        float2 v = __half22float2(hp[j]);
        f[j * 2]     = v.x;
        f[j * 2 + 1] = v.y;
    }
}

template<int D, int ACT>
__global__ __launch_bounds__(256)
void k_agg_half(const __half* __restrict__ h, const float* __restrict__ bias,
                void* __restrict__ outp)
{
    constexpr int L   = D / 8;      // 32 (D=256) or 16 (D=128)
    constexpr int NPB = 256 / L;

    int grp  = threadIdx.x / L;
    int lane = threadIdx.x % L;
    int i = blockIdx.x * NPB + grp;
    if (i >= N_NODES) return;

    const uint4* hv = (const uint4*)h;      // row = L uint4s
    int beg = g_rowptr[i];
    int end = g_rowptr[i + 1];

    float acc[8];
    {
        uint4 r = __ldg(hv + (size_t)i * L + lane);
        float f[8]; unpack8(r, f);
        float dv = g_dinv2[i];
        #pragma unroll
        for (int j = 0; j < 8; j++) acc[j] = dv * f[j];
    }

    int e = beg;
    for (; e + 4 <= end; e += 4) {
        int   s0 = __ldg(g_csrc + e);
        int   s1 = __ldg(g_csrc + e + 1);
        int   s2 = __ldg(g_csrc + e + 2);
        int   s3 = __ldg(g_csrc + e + 3);
        float n0 = __ldg(g_cnorm + e);
        float n1 = __ldg(g_cnorm + e + 1);
        float n2 = __ldg(g_cnorm + e + 2);
        float n3 = __ldg(g_cnorm + e + 3);
        uint4 r0 = __ldg(hv + (size_t)s0 * L + lane);
        uint4 r1 = __ldg(hv + (size_t)s1 * L + lane);
        uint4 r2 = __ldg(hv + (size_t)s2 * L + lane);
        uint4 r3 = __ldg(hv + (size_t)s3 * L + lane);
        float f0[8], f1[8], f2[8], f3[8];
        unpack8(r0, f0); unpack8(r1, f1); unpack8(r2, f2); unpack8(r3, f3);
        #pragma unroll
        for (int j = 0; j < 8; j++) {
            acc[j] += n0 * f0[j];
            acc[j] += n1 * f1[j];
            acc[j] += n2 * f2[j];
            acc[j] += n3 * f3[j];
        }
    }
    for (; e < end; e++) {
        float n = __ldg(g_cnorm + e);
        uint4 r = __ldg(hv + (size_t)__ldg(g_csrc + e) * L + lane);
        float f[8]; unpack8(r, f);
        #pragma unroll
        for (int j = 0; j < 8; j++) acc[j] += n * f[j];
    }

    float4 b0 = __ldg((const float4*)bias + lane * 2);
    float4 b1 = __ldg((const float4*)bias + lane * 2 + 1);
    acc[0] += b0.x; acc[1] += b0.y; acc[2] += b0.z; acc[3] += b0.w;
    acc[4] += b1.x; acc[5] += b1.y; acc[6] += b1.z; acc[7] += b1.w;

    if (ACT == 0) {
        #pragma unroll
        for (int j = 0; j < 8; j++) acc[j] = fmaxf(acc[j], 0.f);
        uint4 r;
        __half2* hp = (__half2*)&r;
        #pragma unroll
        for (int j = 0; j < 4; j++)
            hp[j] = __floats2half2_rn(acc[j * 2], acc[j * 2 + 1]);
        ((uint4*)outp)[(size_t)i * L + lane] = r;
    } else {
        #pragma unroll
        for (int j = 0; j < 8; j++) acc[j] = 1.f / (1.f + expf(-acc[j]));
        float* out = (float*)outp;
        *(float4*)(out + (size_t)i * D + lane * 8)     = make_float4(acc[0], acc[1], acc[2], acc[3]);
        *(float4*)(out + (size_t)i * D + lane * 8 + 4) = make_float4(acc[4], acc[5], acc[6], acc[7]);
    }
}

// ---------------- launch ----------------
extern "C" void kernel_launch(void* const* d_in, const int* in_sizes, int n_in,
                              void* d_out, int out_size)
{
    const float* x  = (const float*)d_in[0];
    const int*   ei = (const int*)d_in[1];      // int32 edge_index [2, E]
    const float* W1 = (const float*)d_in[2];
    const float* b1 = (const float*)d_in[3];
    const float* W2 = (const float*)d_in[4];
    const float* b2 = (const float*)d_in[5];
    float*       out = (float*)d_out;

    const int M  = N_NODES;
    const int nE = N_EDGES;

    __half *h1, *agg1, *h2;
    cudaGetSymbolAddress((void**)&h1,   g_h1);
    cudaGetSymbolAddress((void**)&agg1, g_agg1);
    cudaGetSymbolAddress((void**)&h2,   g_h2);

    // CSR + norm prep
    k_zero_cnt<<<(M  + 255) / 256, 256>>>(M);
    k_count   <<<(nE + 255) / 256, 256>>>(ei, nE);
    k_scan    <<<1, 1024>>>(M);
    k_fill    <<<(nE + 255) / 256, 256>>>(ei, nE);

    dim3 g1(D_HID / 128, (M + 127) / 128);
    dim3 g2(D_OUT / 128, (M + 127) / 128);

    // layer 1: h1 = x @ W1 (half), agg1 = relu(A_norm h1 + b1) (half)
    gemm_tf32<D_HID, false><<<g1, 256>>>(x, W1, h1, M);
    k_agg_half<D_HID, 0><<<(M + 7) / 8, 256>>>(h1, b1, agg1);

    // layer 2: h2 = agg1 @ W2 (half), out = sigmoid(A_norm h2 + b2) (fp32)
    gemm_tf32<D_OUT, true><<<g2, 256>>>(agg1, W2, h2, M);
    k_agg_half<D_OUT, 1><<<(M + 15) / 16, 256>>>(h2, b2, out);
}

// round 7
// speedup vs baseline: 1.4933x; 1.4933x over previous
#include <cuda_runtime.h>
#include <cuda_fp16.h>
#include <cstdint>

#define N_NODES 100000
#define N_EDGES 3200000
#define D_IN    256
#define D_HID   256
#define D_OUT   128

// ---------------- scratch (static device globals; no allocation) ----------------
__device__ __half g_h1  [(size_t)N_NODES * D_HID];   // X @ W1         (half)
__device__ float  g_agg1[(size_t)N_NODES * D_HID];   // relu(agg + b1) (fp32)
__device__ __half g_h2  [(size_t)N_NODES * D_OUT];   // agg1 @ W2      (half)
__device__ int    g_csrc [N_EDGES];                  // CSR: src node per edge (dst-sorted)
__device__ float  g_cnorm[N_EDGES];                  // CSR: edge norm
__device__ int    g_rowptr[N_NODES + 1];
__device__ int    g_cursor[N_NODES];
__device__ int    g_cnt   [N_NODES];                 // incoming-edge count (no self loop)
__device__ float  g_dinv  [N_NODES];
__device__ float  g_dinv2 [N_NODES];

// ---------------- prep ----------------
__global__ void k_zero_cnt(int n) {
    int i = blockIdx.x * blockDim.x + threadIdx.x;
    if (i < n) g_cnt[i] = 0;
}

// edge_index is int32 (JAX x64 disabled)
__global__ void k_count(const int* __restrict__ ei, int nE) {
    int e = blockIdx.x * blockDim.x + threadIdx.x;
    if (e >= nE) return;
    atomicAdd(&g_cnt[ei[nE + e]], 1);
}

// single-block exclusive scan over g_cnt -> g_rowptr, init g_cursor, compute dinv
__global__ void k_scan(int n) {
    const int T = 1024;
    __shared__ int s[T];
    int t = threadIdx.x;
    int items = (n + T - 1) / T;
    int base = t * items;

    int sum = 0;
    for (int j = 0; j < items; j++) {
        int idx = base + j;
        if (idx < n) sum += g_cnt[idx];
    }
    s[t] = sum;
    __syncthreads();
    for (int off = 1; off < T; off <<= 1) {
        int v = (t >= off) ? s[t - off] : 0;
        __syncthreads();
        s[t] += v;
        __syncthreads();
    }
    int run = s[t] - sum;   // exclusive prefix
    for (int j = 0; j < items; j++) {
        int idx = base + j;
        if (idx < n) {
            int c = g_cnt[idx];
            g_rowptr[idx] = run;
            g_cursor[idx] = run;
            run += c;
            float r = rsqrtf((float)(c + 1));   // +1 self loop
            g_dinv[idx]  = r;
            g_dinv2[idx] = r * r;
        }
    }
    if (t == T - 1) g_rowptr[n] = s[T - 1];
}

__global__ void k_fill(const int* __restrict__ ei, int nE) {
    int e = blockIdx.x * blockDim.x + threadIdx.x;
    if (e >= nE) return;
    int s = ei[e];
    int d = ei[nE + e];
    int pos = atomicAdd(&g_cursor[d], 1);
    g_csrc[pos]  = s;
    g_cnorm[pos] = g_dinv[s] * g_dinv[d];
}

// ---------------- TF32 tensor-core GEMM: H(half) = A[M,256] @ W[256,N] --------
// Block tile 128x128, BK=16, 8 warps (2Mx4N), warp tile 64x32 (4x4 m16n8k8 atoms).
// A is fp32. Output stored as half2.
__device__ __forceinline__ uint32_t f2tf32(float f) {
    uint32_t r;
    asm("cvt.rna.tf32.f32 %0, %1;" : "=r"(r) : "f"(f));
    return r;
}

template<int N>
__global__ __launch_bounds__(256, 2)
void gemm_tf32(const float* __restrict__ A, const float* __restrict__ W,
               __half* __restrict__ H, int M)
{
    constexpr int K  = 256;
    constexpr int BK = 16;
    constexpr int ST = 136;                 // smem row stride (floats)
    __shared__ float As[BK * ST];           // [k][m] transposed
    __shared__ float Bs[BK * ST];           // [k][n]

    const int tid   = threadIdx.x;
    const int lane  = tid & 31;
    const int wid   = tid >> 5;
    const int warpM = wid & 1;
    const int warpN = wid >> 1;
    const int g     = lane >> 2;            // groupID 0..7
    const int tig   = lane & 3;             // thread-in-group 0..3

    const int bm = blockIdx.y * 128;
    const int bn = blockIdx.x * 128;

    float c[4][4][4];
    #pragma unroll
    for (int am = 0; am < 4; am++)
        #pragma unroll
        for (int an = 0; an < 4; an++)
            #pragma unroll
            for (int r = 0; r < 4; r++) c[am][an][r] = 0.f;

    for (int k0 = 0; k0 < K; k0 += BK) {
        // ---- load A tile (128 m x 16 k), transpose to As[k][m], tf32-round ----
        #pragma unroll
        for (int it = 0; it < 2; it++) {
            int idx = tid + it * 256;
            int row = idx >> 2;
            int kq  = (idx & 3) * 4;
            float4 av = make_float4(0.f, 0.f, 0.f, 0.f);
            int gm = bm + row;
            if (gm < M)
                av = *(const float4*)(A + (size_t)gm * K + k0 + kq);
            As[(kq + 0) * ST + row] = __uint_as_float(f2tf32(av.x));
            As[(kq + 1) * ST + row] = __uint_as_float(f2tf32(av.y));
            As[(kq + 2) * ST + row] = __uint_as_float(f2tf32(av.z));
            As[(kq + 3) * ST + row] = __uint_as_float(f2tf32(av.w));
        }
        // ---- load B tile (16 k x 128 n) ----
        #pragma unroll
        for (int it = 0; it < 2; it++) {
            int idx  = tid + it * 256;
            int krow = idx >> 5;
            int nq   = (idx & 31) * 4;
            float4 bv = *(const float4*)(W + (size_t)(k0 + krow) * N + bn + nq);
            float4 bt;
            bt.x = __uint_as_float(f2tf32(bv.x));
            bt.y = __uint_as_float(f2tf32(bv.y));
            bt.z = __uint_as_float(f2tf32(bv.z));
            bt.w = __uint_as_float(f2tf32(bv.w));
            *(float4*)&Bs[krow * ST + nq] = bt;
        }
        __syncthreads();

        #pragma unroll
        for (int kk = 0; kk < BK; kk += 8) {
            uint32_t af[4][4];
            #pragma unroll
            for (int am = 0; am < 4; am++) {
                int m0 = warpM * 64 + am * 16 + g;
                af[am][0] = __float_as_uint(As[(kk + tig)     * ST + m0]);
                af[am][1] = __float_as_uint(As[(kk + tig)     * ST + m0 + 8]);
                af[am][2] = __float_as_uint(As[(kk + tig + 4) * ST + m0]);
                af[am][3] = __float_as_uint(As[(kk + tig + 4) * ST + m0 + 8]);
            }
            uint32_t bf[4][2];
            #pragma unroll
            for (int an = 0; an < 4; an++) {
                int n0 = warpN * 32 + an * 8 + g;
                bf[an][0] = __float_as_uint(Bs[(kk + tig)     * ST + n0]);
                bf[an][1] = __float_as_uint(Bs[(kk + tig + 4) * ST + n0]);
            }
            #pragma unroll
            for (int am = 0; am < 4; am++)
                #pragma unroll
                for (int an = 0; an < 4; an++) {
                    asm volatile(
                        "mma.sync.aligned.m16n8k8.row.col.f32.tf32.tf32.f32 "
                        "{%0,%1,%2,%3}, {%4,%5,%6,%7}, {%8,%9}, {%0,%1,%2,%3};"
                        : "+f"(c[am][an][0]), "+f"(c[am][an][1]),
                          "+f"(c[am][an][2]), "+f"(c[am][an][3])
                        : "r"(af[am][0]), "r"(af[am][1]), "r"(af[am][2]), "r"(af[am][3]),
                          "r"(bf[an][0]), "r"(bf[an][1]));
                }
        }
        __syncthreads();
    }

    // ---- epilogue: store half2 pairs ----
    #pragma unroll
    for (int am = 0; am < 4; am++) {
        int row = bm + warpM * 64 + am * 16 + g;
        #pragma unroll
        for (int an = 0; an < 4; an++) {
            int col = bn + warpN * 32 + an * 8 + tig * 2;
            if (row < M)
                *(__half2*)(H + (size_t)row * N + col) =
                    __floats2half2_rn(c[am][an][0], c[am][an][1]);
            if (row + 8 < M)
                *(__half2*)(H + (size_t)(row + 8) * N + col) =
                    __floats2half2_rn(c[am][an][2], c[am][an][3]);
        }
    }
}

// ---------------- CSR aggregation: gather half rows, fp32 accumulate ----------
// R5 loop structure: L = D/4 lanes per node (each lane owns 4 features = uint2),
// NPB = 256/L nodes per block. ACT: 0 = relu, 1 = sigmoid. Output fp32.
__device__ __forceinline__ void unpack4(uint2 r, float* f) {
    float2 a = __half22float2(*(const __half2*)&r.x);
    float2 b = __half22float2(*(const __half2*)&r.y);
    f[0] = a.x; f[1] = a.y; f[2] = b.x; f[3] = b.y;
}

template<int D, int ACT>
__global__ __launch_bounds__(256)
void k_agg_csr(const __half* __restrict__ h, const float* __restrict__ bias,
               float* __restrict__ out)
{
    constexpr int L   = D / 4;      // lanes per node (64 or 32)
    constexpr int NPB = 256 / L;    // nodes per block (4 or 8)

    int grp  = threadIdx.x / L;
    int lane = threadIdx.x % L;
    int i = blockIdx.x * NPB + grp;
    if (i >= N_NODES) return;

    const uint2* hv = (const uint2*)h;      // row = L uint2s (4 halves each)
    int beg = g_rowptr[i];
    int end = g_rowptr[i + 1];

    float acc[4];
    {
        float f[4]; unpack4(__ldg(hv + (size_t)i * L + lane), f);
        float dv = g_dinv2[i];
        #pragma unroll
        for (int j = 0; j < 4; j++) acc[j] = dv * f[j];
    }

    int e = beg;
    for (; e + 4 <= end; e += 4) {
        int   s0 = __ldg(g_csrc + e);
        int   s1 = __ldg(g_csrc + e + 1);
        int   s2 = __ldg(g_csrc + e + 2);
        int   s3 = __ldg(g_csrc + e + 3);
        float n0 = __ldg(g_cnorm + e);
        float n1 = __ldg(g_cnorm + e + 1);
        float n2 = __ldg(g_cnorm + e + 2);
        float n3 = __ldg(g_cnorm + e + 3);
        uint2 r0 = __ldg(hv + (size_t)s0 * L + lane);
        uint2 r1 = __ldg(hv + (size_t)s1 * L + lane);
        uint2 r2 = __ldg(hv + (size_t)s2 * L + lane);
        uint2 r3 = __ldg(hv + (size_t)s3 * L + lane);
        float f0[4], f1[4], f2[4], f3[4];
        unpack4(r0, f0); unpack4(r1, f1); unpack4(r2, f2); unpack4(r3, f3);
        #pragma unroll
        for (int j = 0; j < 4; j++) {
            acc[j] += n0 * f0[j];
            acc[j] += n1 * f1[j];
            acc[j] += n2 * f2[j];
            acc[j] += n3 * f3[j];
        }
    }
    for (; e < end; e++) {
        float n = __ldg(g_cnorm + e);
        float f[4]; unpack4(__ldg(hv + (size_t)__ldg(g_csrc + e) * L + lane), f);
        #pragma unroll
        for (int j = 0; j < 4; j++) acc[j] += n * f[j];
    }

    float4 b = __ldg((const float4*)bias + lane);
    acc[0] += b.x; acc[1] += b.y; acc[2] += b.z; acc[3] += b.w;
    if (ACT == 0) {
        #pragma unroll
        for (int j = 0; j < 4; j++) acc[j] = fmaxf(acc[j], 0.f);
    } else {
        #pragma unroll
        for (int j = 0; j < 4; j++) acc[j] = 1.f / (1.f + expf(-acc[j]));
    }
    *(float4*)(out + (size_t)i * D + lane * 4) =
        make_float4(acc[0], acc[1], acc[2], acc[3]);
}

// ---------------- launch ----------------
extern "C" void kernel_launch(void* const* d_in, const int* in_sizes, int n_in,
                              void* d_out, int out_size)
{
    const float* x  = (const float*)d_in[0];
    const int*   ei = (const int*)d_in[1];      // int32 edge_index [2, E]
    const float* W1 = (const float*)d_in[2];
    const float* b1 = (const float*)d_in[3];
    const float* W2 = (const float*)d_in[4];
    const float* b2 = (const float*)d_in[5];
    float*       out = (float*)d_out;

    const int M  = N_NODES;
    const int nE = N_EDGES;

    __half *h1, *h2;
    float  *agg1;
    cudaGetSymbolAddress((void**)&h1,   g_h1);
    cudaGetSymbolAddress((void**)&agg1, g_agg1);
    cudaGetSymbolAddress((void**)&h2,   g_h2);

    // CSR + norm prep
    k_zero_cnt<<<(M  + 255) / 256, 256>>>(M);
    k_count   <<<(nE + 255) / 256, 256>>>(ei, nE);
    k_scan    <<<1, 1024>>>(M);
    k_fill    <<<(nE + 255) / 256, 256>>>(ei, nE);

    dim3 g1(D_HID / 128, (M + 127) / 128);
    dim3 g2(D_OUT / 128, (M + 127) / 128);

    // layer 1: h1 = x @ W1 (half), agg1 = relu(A_norm h1 + b1) (fp32)
    gemm_tf32<D_HID><<<g1, 256>>>(x, W1, h1, M);
    k_agg_csr<D_HID, 0><<<(M + 3) / 4, 256>>>(h1, b1, agg1);

    // layer 2: h2 = agg1 @ W2 (half), out = sigmoid(A_norm h2 + b2) (fp32)
    gemm_tf32<D_OUT><<<g2, 256>>>(agg1, W2, h2, M);
    k_agg_csr<D_OUT, 1><<<(M + 7) / 8, 256>>>(h2, b2, out);
}

// round 8
// speedup vs baseline: 1.5196x; 1.0176x over previous
#include <cuda_runtime.h>
#include <cuda_fp16.h>
#include <cstdint>

#define N_NODES 100000
#define N_EDGES 3200000
#define D_IN    256
#define D_HID   256
#define D_OUT   128

// ---------------- scratch (static device globals; no allocation) ----------------
__device__ __half g_h1  [(size_t)N_NODES * D_HID];   // X @ W1         (half)
__device__ float  g_agg1[(size_t)N_NODES * D_HID];   // relu(agg + b1) (fp32)
__device__ __half g_h2  [(size_t)N_NODES * D_OUT];   // agg1 @ W2      (half)
__device__ int2   g_edge[N_EDGES];                   // CSR record: (src, norm bits)
__device__ int    g_rowptr[N_NODES + 1];
__device__ int    g_cursor[N_NODES];
__device__ int    g_cnt   [N_NODES];                 // incoming-edge count (no self loop)
__device__ float  g_dinv  [N_NODES];
__device__ float  g_dinv2 [N_NODES];

// ---------------- prep ----------------
__global__ void k_zero_cnt(int n) {
    int i = blockIdx.x * blockDim.x + threadIdx.x;
    if (i < n) g_cnt[i] = 0;
}

// edge_index is int32 (JAX x64 disabled)
__global__ void k_count(const int* __restrict__ ei, int nE) {
    int e = blockIdx.x * blockDim.x + threadIdx.x;
    if (e >= nE) return;
    atomicAdd(&g_cnt[ei[nE + e]], 1);
}

// single-block exclusive scan over g_cnt -> g_rowptr, init g_cursor, compute dinv
__global__ void k_scan(int n) {
    const int T = 1024;
    __shared__ int s[T];
    int t = threadIdx.x;
    int items = (n + T - 1) / T;
    int base = t * items;

    int sum = 0;
    for (int j = 0; j < items; j++) {
        int idx = base + j;
        if (idx < n) sum += g_cnt[idx];
    }
    s[t] = sum;
    __syncthreads();
    for (int off = 1; off < T; off <<= 1) {
        int v = (t >= off) ? s[t - off] : 0;
        __syncthreads();
        s[t] += v;
        __syncthreads();
    }
    int run = s[t] - sum;   // exclusive prefix
    for (int j = 0; j < items; j++) {
        int idx = base + j;
        if (idx < n) {
            int c = g_cnt[idx];
            g_rowptr[idx] = run;
            g_cursor[idx] = run;
            run += c;
            float r = rsqrtf((float)(c + 1));   // +1 self loop
            g_dinv[idx]  = r;
            g_dinv2[idx] = r * r;
        }
    }
    if (t == T - 1) g_rowptr[n] = s[T - 1];
}

__global__ void k_fill(const int* __restrict__ ei, int nE) {
    int e = blockIdx.x * blockDim.x + threadIdx.x;
    if (e >= nE) return;
    int s = ei[e];
    int d = ei[nE + e];
    int pos = atomicAdd(&g_cursor[d], 1);
    g_edge[pos] = make_int2(s, __float_as_int(g_dinv[s] * g_dinv[d]));
}

// ---------------- TF32 tensor-core GEMM: H(half) = A[M,256] @ W[256,N] --------
// Block tile 128x128, BK=16, 8 warps (2Mx4N), warp tile 64x32 (4x4 m16n8k8 atoms).
__device__ __forceinline__ uint32_t f2tf32(float f) {
    uint32_t r;
    asm("cvt.rna.tf32.f32 %0, %1;" : "=r"(r) : "f"(f));
    return r;
}

template<int N>
__global__ __launch_bounds__(256, 2)
void gemm_tf32(const float* __restrict__ A, const float* __restrict__ W,
               __half* __restrict__ H, int M)
{
    constexpr int K  = 256;
    constexpr int BK = 16;
    constexpr int ST = 136;
    __shared__ float As[BK * ST];           // [k][m] transposed
    __shared__ float Bs[BK * ST];           // [k][n]

    const int tid   = threadIdx.x;
    const int lane  = tid & 31;
    const int wid   = tid >> 5;
    const int warpM = wid & 1;
    const int warpN = wid >> 1;
    const int g     = lane >> 2;
    const int tig   = lane & 3;

    const int bm = blockIdx.y * 128;
    const int bn = blockIdx.x * 128;

    float c[4][4][4];
    #pragma unroll
    for (int am = 0; am < 4; am++)
        #pragma unroll
        for (int an = 0; an < 4; an++)
            #pragma unroll
            for (int r = 0; r < 4; r++) c[am][an][r] = 0.f;

    for (int k0 = 0; k0 < K; k0 += BK) {
        #pragma unroll
        for (int it = 0; it < 2; it++) {
            int idx = tid + it * 256;
            int row = idx >> 2;
            int kq  = (idx & 3) * 4;
            float4 av = make_float4(0.f, 0.f, 0.f, 0.f);
            int gm = bm + row;
            if (gm < M)
                av = *(const float4*)(A + (size_t)gm * K + k0 + kq);
            As[(kq + 0) * ST + row] = __uint_as_float(f2tf32(av.x));
            As[(kq + 1) * ST + row] = __uint_as_float(f2tf32(av.y));
            As[(kq + 2) * ST + row] = __uint_as_float(f2tf32(av.z));
            As[(kq + 3) * ST + row] = __uint_as_float(f2tf32(av.w));
        }
        #pragma unroll
        for (int it = 0; it < 2; it++) {
            int idx  = tid + it * 256;
            int krow = idx >> 5;
            int nq   = (idx & 31) * 4;
            float4 bv = *(const float4*)(W + (size_t)(k0 + krow) * N + bn + nq);
            float4 bt;
            bt.x = __uint_as_float(f2tf32(bv.x));
            bt.y = __uint_as_float(f2tf32(bv.y));
            bt.z = __uint_as_float(f2tf32(bv.z));
            bt.w = __uint_as_float(f2tf32(bv.w));
            *(float4*)&Bs[krow * ST + nq] = bt;
        }
        __syncthreads();

        #pragma unroll
        for (int kk = 0; kk < BK; kk += 8) {
            uint32_t af[4][4];
            #pragma unroll
            for (int am = 0; am < 4; am++) {
                int m0 = warpM * 64 + am * 16 + g;
                af[am][0] = __float_as_uint(As[(kk + tig)     * ST + m0]);
                af[am][1] = __float_as_uint(As[(kk + tig)     * ST + m0 + 8]);
                af[am][2] = __float_as_uint(As[(kk + tig + 4) * ST + m0]);
                af[am][3] = __float_as_uint(As[(kk + tig + 4) * ST + m0 + 8]);
            }
            uint32_t bf[4][2];
            #pragma unroll
            for (int an = 0; an < 4; an++) {
                int n0 = warpN * 32 + an * 8 + g;
                bf[an][0] = __float_as_uint(Bs[(kk + tig)     * ST + n0]);
                bf[an][1] = __float_as_uint(Bs[(kk + tig + 4) * ST + n0]);
            }
            #pragma unroll
            for (int am = 0; am < 4; am++)
                #pragma unroll
                for (int an = 0; an < 4; an++) {
                    asm volatile(
                        "mma.sync.aligned.m16n8k8.row.col.f32.tf32.tf32.f32 "
                        "{%0,%1,%2,%3}, {%4,%5,%6,%7}, {%8,%9}, {%0,%1,%2,%3};"
                        : "+f"(c[am][an][0]), "+f"(c[am][an][1]),
                          "+f"(c[am][an][2]), "+f"(c[am][an][3])
                        : "r"(af[am][0]), "r"(af[am][1]), "r"(af[am][2]), "r"(af[am][3]),
                          "r"(bf[an][0]), "r"(bf[an][1]));
                }
        }
        __syncthreads();
    }

    #pragma unroll
    for (int am = 0; am < 4; am++) {
        int row = bm + warpM * 64 + am * 16 + g;
        #pragma unroll
        for (int an = 0; an < 4; an++) {
            int col = bn + warpN * 32 + an * 8 + tig * 2;
            if (row < M)
                *(__half2*)(H + (size_t)row * N + col) =
                    __floats2half2_rn(c[am][an][0], c[am][an][1]);
            if (row + 8 < M)
                *(__half2*)(H + (size_t)(row + 8) * N + col) =
                    __floats2half2_rn(c[am][an][2], c[am][an][3]);
        }
    }
}

// ---------------- CSR aggregation: gather half rows, fp32 accumulate ----------
// L = D/4 lanes per node (each lane owns 4 features = uint2), NPB = 256/L nodes
// per block. 8-deep edge unroll; one int2 edge record per edge.
// ACT: 0 = relu, 1 = sigmoid. Output fp32.
__device__ __forceinline__ void unpack4(uint2 r, float* f) {
    float2 a = __half22float2(*(const __half2*)&r.x);
    float2 b = __half22float2(*(const __half2*)&r.y);
    f[0] = a.x; f[1] = a.y; f[2] = b.x; f[3] = b.y;
}

template<int D, int ACT>
__global__ __launch_bounds__(256)
void k_agg_csr(const __half* __restrict__ h, const float* __restrict__ bias,
               float* __restrict__ out)
{
    constexpr int L   = D / 4;      // lanes per node (64 or 32)
    constexpr int NPB = 256 / L;    // nodes per block (4 or 8)

    int grp  = threadIdx.x / L;
    int lane = threadIdx.x % L;
    int i = blockIdx.x * NPB + grp;
    if (i >= N_NODES) return;

    const uint2* hv = (const uint2*)h;      // row = L uint2s (4 halves each)
    int beg = g_rowptr[i];
    int end = g_rowptr[i + 1];

    float acc[4];
    {
        float f[4]; unpack4(__ldg(hv + (size_t)i * L + lane), f);
        float dv = g_dinv2[i];
        #pragma unroll
        for (int j = 0; j < 4; j++) acc[j] = dv * f[j];
    }

    int e = beg;
    for (; e + 8 <= end; e += 8) {
        int2 er[8];
        #pragma unroll
        for (int u = 0; u < 8; u++) er[u] = __ldg(g_edge + e + u);
        uint2 r[8];
        #pragma unroll
        for (int u = 0; u < 8; u++)
            r[u] = __ldg(hv + (size_t)er[u].x * L + lane);
        #pragma unroll
        for (int u = 0; u < 8; u++) {
            float n = __int_as_float(er[u].y);
            float f[4]; unpack4(r[u], f);
            #pragma unroll
            for (int j = 0; j < 4; j++) acc[j] += n * f[j];
        }
    }
    for (; e < end; e++) {
        int2 er = __ldg(g_edge + e);
        float n = __int_as_float(er.y);
        float f[4]; unpack4(__ldg(hv + (size_t)er.x * L + lane), f);
        #pragma unroll
        for (int j = 0; j < 4; j++) acc[j] += n * f[j];
    }

    float4 b = __ldg((const float4*)bias + lane);
    acc[0] += b.x; acc[1] += b.y; acc[2] += b.z; acc[3] += b.w;
    if (ACT == 0) {
        #pragma unroll
        for (int j = 0; j < 4; j++) acc[j] = fmaxf(acc[j], 0.f);
    } else {
        #pragma unroll
        for (int j = 0; j < 4; j++) acc[j] = 1.f / (1.f + expf(-acc[j]));
    }
    *(float4*)(out + (size_t)i * D + lane * 4) =
        make_float4(acc[0], acc[1], acc[2], acc[3]);
}

// ---------------- launch ----------------
extern "C" void kernel_launch(void* const* d_in, const int* in_sizes, int n_in,
                              void* d_out, int out_size)
{
    const float* x  = (const float*)d_in[0];
    const int*   ei = (const int*)d_in[1];      // int32 edge_index [2, E]
    const float* W1 = (const float*)d_in[2];
    const float* b1 = (const float*)d_in[3];
    const float* W2 = (const float*)d_in[4];
    const float* b2 = (const float*)d_in[5];
    float*       out = (float*)d_out;

    const int M  = N_NODES;
    const int nE = N_EDGES;

    __half *h1, *h2;
    float  *agg1;
    cudaGetSymbolAddress((void**)&h1,   g_h1);
    cudaGetSymbolAddress((void**)&agg1, g_agg1);
    cudaGetSymbolAddress((void**)&h2,   g_h2);

    // CSR + norm prep
    k_zero_cnt<<<(M  + 255) / 256, 256>>>(M);
    k_count   <<<(nE + 255) / 256, 256>>>(ei, nE);
    k_scan    <<<1, 1024>>>(M);
    k_fill    <<<(nE + 255) / 256, 256>>>(ei, nE);

    dim3 g1(D_HID / 128, (M + 127) / 128);
    dim3 g2(D_OUT / 128, (M + 127) / 128);

    // layer 1: h1 = x @ W1 (half), agg1 = relu(A_norm h1 + b1) (fp32)
    gemm_tf32<D_HID><<<g1, 256>>>(x, W1, h1, M);
    k_agg_csr<D_HID, 0><<<(M + 3) / 4, 256>>>(h1, b1, agg1);

    // layer 2: h2 = agg1 @ W2 (half), out = sigmoid(A_norm h2 + b2) (fp32)
    gemm_tf32<D_OUT><<<g2, 256>>>(agg1, W2, h2, M);
    k_agg_csr<D_OUT, 1><<<(M + 7) / 8, 256>>>(h2, b2, out);
}